// round 4
// baseline (speedup 1.0000x reference)
#include <cuda_runtime.h>
#include <math.h>

#define B    8
#define NN   1024
#define CIN  256
#define COUT 256
#define RR   4
#define HH   4
#define ALPHA 0.2f

typedef unsigned long long ull;

// -------- packed f32x2 helpers (sm_103a FFMA2) --------
__device__ __forceinline__ ull dup2(float x) {
    ull r; asm("mov.b64 %0, {%1, %1};" : "=l"(r) : "f"(x)); return r;
}
__device__ __forceinline__ void fma2(ull& d, ull a, ull b) {
    asm("fma.rn.f32x2 %0, %1, %2, %3;" : "=l"(d) : "l"(a), "l"(b), "l"(d));
}
__device__ __forceinline__ void unpack2(float& lo, float& hi, ull v) {
    asm("mov.b64 {%0, %1}, %2;" : "=f"(lo), "=f"(hi) : "l"(v));
}

// -------- scratch --------
__device__ float g_F[(size_t)RR * B * NN * COUT];
__device__ float g_E1 [RR * B * HH * NN];
__device__ float g_E2 [RR * B * HH * NN];
__device__ float g_T  [RR * B * HH * NN];
__device__ float g_A1p[RR * B * HH * NN];
__device__ float g_A2p[RR * B * HH * NN];
__device__ float g_A1 [RR * B * HH * NN];
__device__ float g_A2 [RR * B * HH * NN];
__device__ unsigned g_mask[B * NN * RR * (NN / 32)];

#define LIDX(r, b, h, n) ((((r) * B + (b)) * HH + (h)) * NN + (n))

// -------- kernel 0: zero output --------
__global__ void k_zero(float* __restrict__ out, int nel) {
    int i = blockIdx.x * 256 + threadIdx.x;
    if (i < nel) out[i] = 0.f;
}

// -------- kernel 1: F_r = X @ W[r], FFMA2, thread tile 16m x 8n --------
__global__ __launch_bounds__(128, 2) void k_gemm(const float* __restrict__ X,
                                                 const float* __restrict__ W) {
    int r  = blockIdx.z;
    int m0 = blockIdx.y * 128;
    int d0 = blockIdx.x * 128;
    int tid = threadIdx.x;
    int mg = tid >> 4;          // 0..7  (16 rows each)
    int ng = tid & 15;          // 0..15 (8 cols each)
    __shared__ float As[8][128];   // [k][m]
    __shared__ float Bs[8][128];   // [k][n]
    const float* Wr = W + (size_t)r * CIN * COUT;

    ull acc[16][4];
#pragma unroll
    for (int m = 0; m < 16; m++)
#pragma unroll
        for (int c = 0; c < 4; c++) acc[m][c] = 0ull;

    for (int k0 = 0; k0 < CIN; k0 += 8) {
        {
            int row = tid;   // 0..127
            const float* xp = X + (size_t)(m0 + row) * CIN + k0;
            float4 a0 = *(const float4*)xp;
            float4 a1 = *(const float4*)(xp + 4);
            As[0][row] = a0.x; As[1][row] = a0.y; As[2][row] = a0.z; As[3][row] = a0.w;
            As[4][row] = a1.x; As[5][row] = a1.y; As[6][row] = a1.z; As[7][row] = a1.w;
        }
#pragma unroll
        for (int u = 0; u < 2; u++) {
            int idx = tid + u * 128;
            int krow = idx >> 5, dq = (idx & 31) * 4;
            *(float4*)&Bs[krow][dq] =
                *(const float4*)(Wr + (size_t)(k0 + krow) * COUT + d0 + dq);
        }
        __syncthreads();
#pragma unroll
        for (int kk = 0; kk < 8; kk++) {
            float4 av0 = *(float4*)&As[kk][mg * 16];
            float4 av1 = *(float4*)&As[kk][mg * 16 + 4];
            float4 av2 = *(float4*)&As[kk][mg * 16 + 8];
            float4 av3 = *(float4*)&As[kk][mg * 16 + 12];
            float a[16] = {av0.x, av0.y, av0.z, av0.w, av1.x, av1.y, av1.z, av1.w,
                           av2.x, av2.y, av2.z, av2.w, av3.x, av3.y, av3.z, av3.w};
            ulonglong2 b01 = *(ulonglong2*)&Bs[kk][ng * 8];
            ulonglong2 b23 = *(ulonglong2*)&Bs[kk][ng * 8 + 4];
#pragma unroll
            for (int m = 0; m < 16; m++) {
                ull ad = dup2(a[m]);
                fma2(acc[m][0], ad, b01.x);
                fma2(acc[m][1], ad, b01.y);
                fma2(acc[m][2], ad, b23.x);
                fma2(acc[m][3], ad, b23.y);
            }
        }
        __syncthreads();
    }
    float* Fo = g_F + (size_t)r * (B * NN) * COUT;
#pragma unroll
    for (int m = 0; m < 16; m++) {
        float v[8];
#pragma unroll
        for (int c = 0; c < 4; c++) unpack2(v[c * 2], v[c * 2 + 1], acc[m][c]);
        float* op = Fo + (size_t)(m0 + mg * 16 + m) * COUT + d0 + ng * 8;
        *(float4*)op = make_float4(v[0], v[1], v[2], v[3]);
        *(float4*)(op + 4) = make_float4(v[4], v[5], v[6], v[7]);
    }
}

// -------- kernel 2: li/lj dots + exp factor tables --------
__global__ __launch_bounds__(256) void k_lvec(const float* __restrict__ a) {
    int warp = threadIdx.x >> 5, lane = threadIdx.x & 31;
    int rbn = blockIdx.x * 8 + warp;
    int r = rbn >> 13;
    int bn = rbn & 8191;
    int b = bn >> 10, n = bn & 1023;
    const float* f = g_F + (size_t)rbn * COUT;
#pragma unroll
    for (int h = 0; h < HH; h++) {
        const float* ah = a + (r * HH + h) * 128;
        float f1 = f[h * 64 + lane];
        float f2 = f[h * 64 + 32 + lane];
        float li = f1 * ah[lane]      + f2 * ah[32 + lane];
        float lj = f1 * ah[64 + lane] + f2 * ah[96 + lane];
#pragma unroll
        for (int o = 16; o > 0; o >>= 1) {
            li += __shfl_xor_sync(~0u, li, o);
            lj += __shfl_xor_sync(~0u, lj, o);
        }
        if (lane == 0) {
            int idx = LIDX(r, b, h, n);
            g_E1[idx]  = expf(lj);
            g_E2[idx]  = expf(ALPHA * lj);
            g_T[idx]   = expf(-li);
            g_A1p[idx] = expf(li);
            g_A2p[idx] = expf(ALPHA * li);
        }
    }
}

// -------- kernel 3a: streaming adjacency bit-pack --------
__global__ __launch_bounds__(256) void k_pack(const int* __restrict__ adj) {
    int w    = (blockIdx.x * 256 + threadIdx.x) >> 5;
    int lane = threadIdx.x & 31;
    int jw = w & 31;
    int i  = (w >> 5) & 1023;
    int b  = w >> 15;
    int j  = jw * 32 + lane;
    const int4 av = *(const int4*)(adj + ((size_t)(b * NN + i) * NN + j) * RR);
    unsigned m0 = __ballot_sync(~0u, av.x != 0);
    unsigned m1 = __ballot_sync(~0u, av.y != 0);
    unsigned m2 = __ballot_sync(~0u, av.z != 0);
    unsigned m3 = __ballot_sync(~0u, av.w != 0);
    if (lane < 4) {
        unsigned mv = (lane == 0) ? m0 : (lane == 1) ? m1 : (lane == 2) ? m2 : m3;
        g_mask[(((size_t)b * NN + i) * RR + lane) * (NN / 32) + jw] = mv;
    }
}

// -------- kernel 3b: softmax denominators from packed bits --------
#define JC 256
__global__ __launch_bounds__(256) void k_denom() {
    int b  = blockIdx.y;
    int i0 = blockIdx.x * 8;
    int warp = threadIdx.x >> 5, lane = threadIdx.x & 31;
    int i = i0 + warp;
    int bn = b * NN + i;
    __shared__ float sE1[16][JC];
    __shared__ float sE2[16][JC];

    float T[16], s1[16], s2[16];
#pragma unroll
    for (int rh = 0; rh < 16; rh++) {
        int r = rh >> 2, h = rh & 3;
        T[rh] = g_T[LIDX(r, b, h, i)];
        s1[rh] = 0.f; s2[rh] = 0.f;
    }

    for (int jc = 0; jc < NN; jc += JC) {
        __syncthreads();
        for (int idx = threadIdx.x; idx < 16 * JC; idx += 256) {
            int rh = idx / JC, jj = idx % JC;
            int r = rh >> 2, h = rh & 3;
            int g = LIDX(r, b, h, jc + jj);
            sE1[rh][jj] = g_E1[g];
            sE2[rh][jj] = g_E2[g];
        }
        __syncthreads();
        for (int js = 0; js < JC; js += 32) {
            int jword = (jc + js) >> 5;
            unsigned mw[4];
#pragma unroll
            for (int r = 0; r < 4; r++)
                mw[r] = g_mask[(((size_t)bn) * RR + r) * (NN / 32) + jword];
#pragma unroll
            for (int rh = 0; rh < 16; rh++) {
                if ((mw[rh >> 2] >> lane) & 1u) {
                    float e1 = sE1[rh][js + lane];
                    float e2 = sE2[rh][js + lane];
                    if (e1 > T[rh]) s1[rh] += e1; else s2[rh] += e2;
                }
            }
        }
    }
#pragma unroll
    for (int rh = 0; rh < 16; rh++) {
#pragma unroll
        for (int o = 16; o > 0; o >>= 1) {
            s1[rh] += __shfl_xor_sync(~0u, s1[rh], o);
            s2[rh] += __shfl_xor_sync(~0u, s2[rh], o);
        }
    }
#pragma unroll
    for (int rh = 0; rh < 16; rh++) {
        if (lane == rh) {
            int r = rh >> 2, h = rh & 3;
            int idx = LIDX(r, b, h, i);
            float A1 = g_A1p[idx], A2 = g_A2p[idx];
            float den = A1 * s1[rh] + A2 * s2[rh];
            if (!(den > 0.f)) { den = 1.f; A1 = 0.f; A2 = 0.f; }
            g_A1[idx] = A1 / den;
            g_A2[idx] = A2 / den;
        }
    }
}

// -------- kernel 4: out += P @ F, FFMA2, thread tile 16i x 8c (one h) --------
// block: 64 i-rows x 256 cols, 128 threads; rg=row group (16 rows), cg->h+8 cols
__global__ __launch_bounds__(128, 2) void k_pv(float* __restrict__ out) {
    int b = blockIdx.z, r = blockIdx.y, i0 = blockIdx.x * 64;
    int tid = threadIdx.x;
    int rg = tid >> 5;           // 0..3
    int cg = tid & 31;           // 0..31
    int h  = cg >> 3;            // 0..3
    int c0 = h * 64 + (cg & 7) * 8;

    __shared__ float Fsh[16][256];          // 16 KB
    __shared__ float Psh[16][4][68];        // padded: h-lines on distinct banks
    __shared__ float sT[4][64], sA1[4][64], sA2[4][64];
    __shared__ float sE1t[16][4], sE2t[16][4];
    __shared__ unsigned smask[64];

#pragma unroll
    for (int u = 0; u < 2; u++) {
        int idx = tid + u * 128;
        int h2 = idx >> 6, ii = idx & 63;
        int g = LIDX(r, b, h2, i0 + ii);
        sT[h2][ii]  = g_T[g];
        sA1[h2][ii] = g_A1[g];
        sA2[h2][ii] = g_A2[g];
    }

    ull acc[16][4];
#pragma unroll
    for (int i = 0; i < 16; i++)
#pragma unroll
        for (int c = 0; c < 4; c++) acc[i][c] = 0ull;

    const float* Fbase = g_F + (size_t)(r * B + b) * NN * COUT;

    for (int jt = 0; jt < NN; jt += 16) {
        __syncthreads();
#pragma unroll
        for (int u = 0; u < 8; u++) {
            int idx = tid + u * 128;
            int row = idx >> 6, c4 = idx & 63;
            *(float4*)&Fsh[row][c4 * 4] =
                *(const float4*)(Fbase + (size_t)(jt + row) * COUT + c4 * 4);
        }
        if (tid < 64) {
            int j = tid >> 2, hh = tid & 3;
            sE1t[j][hh] = g_E1[LIDX(r, b, hh, jt + j)];
            sE2t[j][hh] = g_E2[LIDX(r, b, hh, jt + j)];
        }
        if ((jt & 31) == 0 && tid < 64) {
            smask[tid] = g_mask[(((size_t)b * NN + i0 + tid) * RR + r) * (NN / 32) + (jt >> 5)];
        }
        __syncthreads();

        int shift = jt & 16;
#pragma unroll
        for (int u = 0; u < 32; u++) {
            int e = tid + u * 128;           // 0..4095 : j*256 + hh*64 + ii
            int ii = e & 63, hh = (e >> 6) & 3, j = e >> 8;
            unsigned bit = (smask[ii] >> (shift + j)) & 1u;
            float p = 0.f;
            if (bit) {
                float e1 = sE1t[j][hh];
                p = (e1 > sT[hh][ii]) ? sA1[hh][ii] * e1 : sA2[hh][ii] * sE2t[j][hh];
            }
            Psh[j][hh][ii] = p;
        }
        __syncthreads();

#pragma unroll
        for (int j = 0; j < 16; j++) {
            float4 p0 = *(float4*)&Psh[j][h][rg * 16];
            float4 p1 = *(float4*)&Psh[j][h][rg * 16 + 4];
            float4 p2 = *(float4*)&Psh[j][h][rg * 16 + 8];
            float4 p3 = *(float4*)&Psh[j][h][rg * 16 + 12];
            float p[16] = {p0.x, p0.y, p0.z, p0.w, p1.x, p1.y, p1.z, p1.w,
                           p2.x, p2.y, p2.z, p2.w, p3.x, p3.y, p3.z, p3.w};
            ulonglong2 fA = *(ulonglong2*)&Fsh[j][c0];
            ulonglong2 fB = *(ulonglong2*)&Fsh[j][c0 + 4];
#pragma unroll
            for (int i = 0; i < 16; i++) {
                ull pd = dup2(p[i]);
                fma2(acc[i][0], pd, fA.x);
                fma2(acc[i][1], pd, fA.y);
                fma2(acc[i][2], pd, fB.x);
                fma2(acc[i][3], pd, fB.y);
            }
        }
    }

#pragma unroll
    for (int i = 0; i < 16; i++) {
        float v[8];
#pragma unroll
        for (int c = 0; c < 4; c++) unpack2(v[c * 2], v[c * 2 + 1], acc[i][c]);
        float* op = out + (size_t)(b * NN + i0 + rg * 16 + i) * COUT + c0;
#pragma unroll
        for (int c = 0; c < 8; c++) atomicAdd(&op[c], v[c]);
    }
}

// -------- launch --------
extern "C" void kernel_launch(void* const* d_in, const int* in_sizes, int n_in,
                              void* d_out, int out_size) {
    const float* X   = (const float*)d_in[0];
    const int*   adj = (const int*)d_in[1];
    const float* W   = (const float*)d_in[2];
    const float* a   = (const float*)d_in[3];
    float* out = (float*)d_out;

    k_zero<<<(out_size + 255) / 256, 256>>>(out, out_size);
    k_gemm<<<dim3(COUT / 128, (B * NN) / 128, RR), 128>>>(X, W);
    k_lvec<<<(RR * B * NN) / 8, 256>>>(a);
    k_pack<<<(B * NN * 32) / 8, 256>>>(adj);
    k_denom<<<dim3(NN / 8, B), 256>>>();
    k_pv<<<dim3(NN / 64, RR, B), 128>>>(out);
}

// round 8
// speedup vs baseline: 1.5022x; 1.5022x over previous
#include <cuda_runtime.h>
#include <math.h>
#include <stdint.h>

#define B    8
#define NN   1024
#define CIN  256
#define COUT 256
#define RR   4
#define HH   4
#define ALPHA 0.2f

// -------- scratch --------
__device__ float g_F[(size_t)RR * B * NN * COUT];
__device__ unsigned g_Fhi[(size_t)RR * B * COUT * NN / 2];  // bf16 pairs, [rb][c][j/2]
__device__ unsigned g_Flo[(size_t)RR * B * COUT * NN / 2];
__device__ float g_E1 [RR * B * HH * NN];
__device__ float g_E2 [RR * B * HH * NN];
__device__ float g_T  [RR * B * HH * NN];
__device__ float g_A1p[RR * B * HH * NN];
__device__ float g_A2p[RR * B * HH * NN];
__device__ float g_A1 [RR * B * HH * NN];
__device__ float g_A2 [RR * B * HH * NN];
__device__ __align__(16) unsigned g_mask[B * NN * RR * (NN / 32)];

#define LIDX(r, b, h, n) ((((r) * B + (b)) * HH + (h)) * NN + (n))

// -------- helpers --------
__device__ __forceinline__ uint32_t smem_u32(const void* p) {
    uint32_t a;
    asm("{ .reg .u64 t; cvta.to.shared.u64 t, %1; cvt.u32.u64 %0, t; }" : "=r"(a) : "l"(p));
    return a;
}
__device__ __forceinline__ uint32_t sw128(uint32_t o) { return o ^ ((o >> 3) & 0x70); }

__device__ __forceinline__ void ldm_x2(unsigned& r0, unsigned& r1, uint32_t addr) {
    asm volatile("ldmatrix.sync.aligned.m8n8.x2.shared.b16 {%0,%1}, [%2];"
                 : "=r"(r0), "=r"(r1) : "r"(addr));
}
__device__ __forceinline__ void mma_bf16(float* c, unsigned a0, unsigned a1,
                                         unsigned a2, unsigned a3,
                                         unsigned b0, unsigned b1) {
    asm("mma.sync.aligned.m16n8k16.row.col.f32.bf16.bf16.f32 "
        "{%0,%1,%2,%3}, {%4,%5,%6,%7}, {%8,%9}, {%0,%1,%2,%3};"
        : "+f"(c[0]), "+f"(c[1]), "+f"(c[2]), "+f"(c[3])
        : "r"(a0), "r"(a1), "r"(a2), "r"(a3), "r"(b0), "r"(b1));
}
__device__ __forceinline__ float pvf(unsigned mw, int bit, float e1, float e2,
                                     float T, float A1, float A2) {
    float p = (e1 > T) ? A1 * e1 : A2 * e2;
    return ((mw >> bit) & 1u) ? p : 0.f;
}
__device__ __forceinline__ void split2(float v0, float v1, unsigned& hi, unsigned& lo) {
    unsigned u0 = __float_as_uint(v0), u1 = __float_as_uint(v1);
    hi = __byte_perm(u0, u1, 0x7632);
    float l0 = v0 - __uint_as_float(u0 & 0xFFFF0000u);
    float l1 = v1 - __uint_as_float(u1 & 0xFFFF0000u);
    lo = __byte_perm(__float_as_uint(l0), __float_as_uint(l1), 0x7632);
}

// SMEM layout for k_pv_mma
#define SM_E2   16384
#define SM_MASK 32768
#define SM_FH   43008
#define SM_FL   (43008 + 32768)
#define SMEM_PV (43008 + 65536)

// -------- kernel 1: F_r = X @ W[r]  (scalar, proven) --------
__global__ __launch_bounds__(256) void k_gemm(const float* __restrict__ X,
                                              const float* __restrict__ W) {
    int r  = blockIdx.z;
    int m0 = blockIdx.y * 128;
    int d0 = blockIdx.x * 128;
    __shared__ float As[8][128];
    __shared__ float Bs[8][128];
    const float* Wr = W + (size_t)r * CIN * COUT;
    float acc[8][8];
#pragma unroll
    for (int i = 0; i < 8; i++)
#pragma unroll
        for (int j = 0; j < 8; j++) acc[i][j] = 0.f;
    int tid = threadIdx.x;
    int tx = tid & 15, ty = tid >> 4;
    for (int k0 = 0; k0 < CIN; k0 += 8) {
        {
            int row = tid >> 1;
            int kq  = (tid & 1) * 4;
            float4 va = *(const float4*)(X + (size_t)(m0 + row) * CIN + k0 + kq);
            As[kq + 0][row] = va.x; As[kq + 1][row] = va.y;
            As[kq + 2][row] = va.z; As[kq + 3][row] = va.w;
        }
        {
            int krow = tid >> 5;
            int dq   = (tid & 31) * 4;
            *(float4*)&Bs[krow][dq] =
                *(const float4*)(Wr + (size_t)(k0 + krow) * COUT + d0 + dq);
        }
        __syncthreads();
#pragma unroll
        for (int kk = 0; kk < 8; kk++) {
            float av[8], bv[8];
            *(float4*)&av[0] = *(float4*)&As[kk][ty * 8];
            *(float4*)&av[4] = *(float4*)&As[kk][ty * 8 + 4];
            *(float4*)&bv[0] = *(float4*)&Bs[kk][tx * 8];
            *(float4*)&bv[4] = *(float4*)&Bs[kk][tx * 8 + 4];
#pragma unroll
            for (int i = 0; i < 8; i++)
#pragma unroll
                for (int j = 0; j < 8; j++)
                    acc[i][j] = fmaf(av[i], bv[j], acc[i][j]);
        }
        __syncthreads();
    }
    float* Fo = g_F + (size_t)r * (B * NN) * COUT;
#pragma unroll
    for (int i = 0; i < 8; i++) {
        int m = m0 + ty * 8 + i;
#pragma unroll
        for (int jq = 0; jq < 8; jq += 4) {
            float4 v = make_float4(acc[i][jq], acc[i][jq + 1], acc[i][jq + 2], acc[i][jq + 3]);
            *(float4*)(Fo + (size_t)m * COUT + d0 + tx * 8 + jq) = v;
        }
    }
}

// -------- kernel 1b: transpose+split F -> bf16 hi/lo planes [rb][c][j] --------
__global__ __launch_bounds__(256) void k_split() {
    int rb = blockIdx.z;
    int jt = blockIdx.x;
    int ct = blockIdx.y;
    __shared__ float sm[32][33];
    int t = threadIdx.x;
    {
        int tx = t & 31, ty = t >> 5;
#pragma unroll
        for (int u = 0; u < 4; u++) {
            int jj = ty + u * 8;
            sm[jj][tx] = g_F[((size_t)rb * NN + jt * 32 + jj) * COUT + ct * 32 + tx];
        }
    }
    __syncthreads();
    {
        int tx2 = t & 15, cy = t >> 4;
#pragma unroll
        for (int u = 0; u < 2; u++) {
            int c = cy + u * 16;
            float p0 = sm[2 * tx2][c];
            float p1 = sm[2 * tx2 + 1][c];
            unsigned hiw, low;
            split2(p0, p1, hiw, low);
            size_t idx = ((size_t)rb * 256 + ct * 32 + c) * 512 + jt * 16 + tx2;
            g_Fhi[idx] = hiw;
            g_Flo[idx] = low;
        }
    }
}

// -------- kernel 2: li/lj dots + exp factor tables --------
__global__ __launch_bounds__(256) void k_lvec(const float* __restrict__ a) {
    int warp = threadIdx.x >> 5, lane = threadIdx.x & 31;
    int rbn = blockIdx.x * 8 + warp;
    int r = rbn >> 13;
    int bn = rbn & 8191;
    int b = bn >> 10, n = bn & 1023;
    const float* f = g_F + (size_t)rbn * COUT;
#pragma unroll
    for (int h = 0; h < HH; h++) {
        const float* ah = a + (r * HH + h) * 128;
        float f1 = f[h * 64 + lane];
        float f2 = f[h * 64 + 32 + lane];
        float li = f1 * ah[lane]      + f2 * ah[32 + lane];
        float lj = f1 * ah[64 + lane] + f2 * ah[96 + lane];
#pragma unroll
        for (int o = 16; o > 0; o >>= 1) {
            li += __shfl_xor_sync(~0u, li, o);
            lj += __shfl_xor_sync(~0u, lj, o);
        }
        if (lane == 0) {
            int idx = LIDX(r, b, h, n);
            g_E1[idx]  = expf(lj);
            g_E2[idx]  = expf(ALPHA * lj);
            g_T[idx]   = expf(-li);
            g_A1p[idx] = expf(li);
            g_A2p[idx] = expf(ALPHA * li);
        }
    }
}

// -------- kernel 3a: streaming adjacency bit-pack --------
__global__ __launch_bounds__(256) void k_pack(const int* __restrict__ adj) {
    int w    = (blockIdx.x * 256 + threadIdx.x) >> 5;
    int lane = threadIdx.x & 31;
    int jw = w & 31;
    int i  = (w >> 5) & 1023;
    int b  = w >> 15;
    int j  = jw * 32 + lane;
    const int4 av = *(const int4*)(adj + ((size_t)(b * NN + i) * NN + j) * RR);
    unsigned m0 = __ballot_sync(~0u, av.x != 0);
    unsigned m1 = __ballot_sync(~0u, av.y != 0);
    unsigned m2 = __ballot_sync(~0u, av.z != 0);
    unsigned m3 = __ballot_sync(~0u, av.w != 0);
    if (lane < 4) {
        unsigned mv = (lane == 0) ? m0 : (lane == 1) ? m1 : (lane == 2) ? m2 : m3;
        g_mask[(((size_t)b * NN + i) * RR + lane) * (NN / 32) + jw] = mv;
    }
}

// -------- kernel 3b: softmax denominators from packed bits --------
#define JC 256
__global__ __launch_bounds__(256) void k_denom() {
    int b  = blockIdx.y;
    int i0 = blockIdx.x * 8;
    int warp = threadIdx.x >> 5, lane = threadIdx.x & 31;
    int i = i0 + warp;
    int bn = b * NN + i;
    __shared__ float sE1[16][JC];
    __shared__ float sE2[16][JC];
    float T[16], s1[16], s2[16];
#pragma unroll
    for (int rh = 0; rh < 16; rh++) {
        int r = rh >> 2, h = rh & 3;
        T[rh] = g_T[LIDX(r, b, h, i)];
        s1[rh] = 0.f; s2[rh] = 0.f;
    }
    for (int jc = 0; jc < NN; jc += JC) {
        __syncthreads();
        for (int idx = threadIdx.x; idx < 16 * JC; idx += 256) {
            int rh = idx / JC, jj = idx % JC;
            int r = rh >> 2, h = rh & 3;
            int g = LIDX(r, b, h, jc + jj);
            sE1[rh][jj] = g_E1[g];
            sE2[rh][jj] = g_E2[g];
        }
        __syncthreads();
        for (int js = 0; js < JC; js += 32) {
            int jword = (jc + js) >> 5;
            unsigned mw[4];
#pragma unroll
            for (int r = 0; r < 4; r++)
                mw[r] = g_mask[(((size_t)bn) * RR + r) * (NN / 32) + jword];
#pragma unroll
            for (int rh = 0; rh < 16; rh++) {
                if ((mw[rh >> 2] >> lane) & 1u) {
                    float e1 = sE1[rh][js + lane];
                    float e2 = sE2[rh][js + lane];
                    if (e1 > T[rh]) s1[rh] += e1; else s2[rh] += e2;
                }
            }
        }
    }
#pragma unroll
    for (int rh = 0; rh < 16; rh++) {
#pragma unroll
        for (int o = 16; o > 0; o >>= 1) {
            s1[rh] += __shfl_xor_sync(~0u, s1[rh], o);
            s2[rh] += __shfl_xor_sync(~0u, s2[rh], o);
        }
    }
#pragma unroll
    for (int rh = 0; rh < 16; rh++) {
        if (lane == rh) {
            int r = rh >> 2, h = rh & 3;
            int idx = LIDX(r, b, h, i);
            float A1 = g_A1p[idx], A2 = g_A2p[idx];
            float den = A1 * s1[rh] + A2 * s2[rh];
            if (!(den > 0.f)) { den = 1.f; A1 = 0.f; A2 = 0.f; }
            g_A1[idx] = A1 / den;
            g_A2[idx] = A2 / den;
        }
    }
}

// -------- kernel 4: PV via mma.sync bf16 (3-product hi/lo split) --------
// block (i-tile 64, b); 8 warps; warp w: tasks (isub=w&3, h=w>>2) and (isub, h+2)
// A (P) built directly in fragment registers; B (F^T hi/lo) staged+ldmatrix.
__global__ __launch_bounds__(256, 1) void k_pv_mma(float* __restrict__ out) {
    extern __shared__ __align__(128) char smem[];
    float* sE1 = (float*)(smem);
    float* sE2 = (float*)(smem + SM_E2);
    unsigned* smask = (unsigned*)(smem + SM_MASK);   // [64][33] padded
    uint32_t sb = smem_u32(smem);

    int b = blockIdx.y, i0 = blockIdx.x * 64;
    int tid = threadIdx.x;
    int wid = tid >> 5, lane = tid & 31;
    int g = lane >> 2, c = lane & 3;
    int isub = wid & 3;
    int h0 = wid >> 2;              // task0 head; task1 head = h0+2
    int rowl = isub * 16 + g;       // local row 0..63
    int rowh = rowl + 8;

    float acc[2][8][4];
#pragma unroll
    for (int t = 0; t < 2; t++)
#pragma unroll
        for (int nf = 0; nf < 8; nf++)
#pragma unroll
            for (int q = 0; q < 4; q++) acc[t][nf][q] = 0.f;

    for (int r = 0; r < RR; r++) {
        int rb = r * B + b;
        __syncthreads();
        // stage E tables (coalesced)
#pragma unroll
        for (int u = 0; u < 16; u++) {
            int idx = u * 256 + tid;
            sE1[idx] = g_E1[rb * 4096 + idx];
            sE2[idx] = g_E2[rb * 4096 + idx];
        }
        // stage masks [64][33]
#pragma unroll
        for (int u = 0; u < 8; u++) {
            int idx = u * 256 + tid;
            int row = idx >> 5, w = idx & 31;
            smask[row * 33 + w] =
                g_mask[(((size_t)b * NN + i0 + row) * RR + r) * 32 + w];
        }
        // per-task row constants
        float Tc[2][2], A1c[2][2], A2c[2][2];
#pragma unroll
        for (int t = 0; t < 2; t++) {
            int h = h0 + 2 * t;
            int base = rb * 4096 + h * 1024 + i0;
            Tc[t][0]  = g_T [base + rowl];  Tc[t][1]  = g_T [base + rowh];
            A1c[t][0] = g_A1[base + rowl];  A1c[t][1] = g_A1[base + rowh];
            A2c[t][0] = g_A2[base + rowl];  A2c[t][1] = g_A2[base + rowh];
        }

        for (int jc = 0; jc < NN; jc += 64) {
            __syncthreads();
            // stage F^T hi/lo chunk: row = channel tid, 64 j's, SW128
            {
                const uint4* ph = (const uint4*)(g_Fhi + ((size_t)rb * 256 + tid) * 512 + jc / 2);
                const uint4* pl = (const uint4*)(g_Flo + ((size_t)rb * 256 + tid) * 512 + jc / 2);
#pragma unroll
                for (int q = 0; q < 8; q++) {
                    uint32_t off = sw128((uint32_t)(tid * 128 + q * 16));
                    *(uint4*)(smem + SM_FH + off) = ph[q];
                    *(uint4*)(smem + SM_FL + off) = pl[q];
                }
            }
            __syncthreads();

#pragma unroll
            for (int kf = 0; kf < 4; kf++) {
                int jb = jc + kf * 16;
                unsigned mwl = smask[rowl * 33 + (jb >> 5)];
                unsigned mwh = smask[rowh * 33 + (jb >> 5)];
                int bo = jb & 31;                 // 0 or 16
#pragma unroll
                for (int t = 0; t < 2; t++) {
                    int h = h0 + 2 * t;
                    int eb = h * 1024 + jb + 2 * c;
                    float2 e1a = *(float2*)&sE1[eb];
                    float2 e1b = *(float2*)&sE1[eb + 8];
                    float2 e2a = *(float2*)&sE2[eb];
                    float2 e2b = *(float2*)&sE2[eb + 8];
                    float p00 = pvf(mwl, bo + 2*c,     e1a.x, e2a.x, Tc[t][0], A1c[t][0], A2c[t][0]);
                    float p01 = pvf(mwl, bo + 2*c + 1, e1a.y, e2a.y, Tc[t][0], A1c[t][0], A2c[t][0]);
                    float p02 = pvf(mwl, bo + 8 + 2*c,     e1b.x, e2b.x, Tc[t][0], A1c[t][0], A2c[t][0]);
                    float p03 = pvf(mwl, bo + 8 + 2*c + 1, e1b.y, e2b.y, Tc[t][0], A1c[t][0], A2c[t][0]);
                    float p10 = pvf(mwh, bo + 2*c,     e1a.x, e2a.x, Tc[t][1], A1c[t][1], A2c[t][1]);
                    float p11 = pvf(mwh, bo + 2*c + 1, e1a.y, e2a.y, Tc[t][1], A1c[t][1], A2c[t][1]);
                    float p12 = pvf(mwh, bo + 8 + 2*c,     e1b.x, e2b.x, Tc[t][1], A1c[t][1], A2c[t][1]);
                    float p13 = pvf(mwh, bo + 8 + 2*c + 1, e1b.y, e2b.y, Tc[t][1], A1c[t][1], A2c[t][1]);
                    unsigned ah0, ah1, ah2, ah3, al0, al1, al2, al3;
                    split2(p00, p01, ah0, al0);
                    split2(p10, p11, ah1, al1);
                    split2(p02, p03, ah2, al2);
                    split2(p12, p13, ah3, al3);
#pragma unroll
                    for (int nf = 0; nf < 8; nf++) {
                        int lr = h * 64 + nf * 8 + (lane & 7);
                        int jo2 = kf * 32 + ((lane >> 3) & 1) * 16;
                        uint32_t off = sw128((uint32_t)(lr * 128 + jo2));
                        unsigned bh0, bh1, bl0, bl1;
                        ldm_x2(bh0, bh1, sb + SM_FH + off);
                        ldm_x2(bl0, bl1, sb + SM_FL + off);
                        mma_bf16(acc[t][nf], ah0, ah1, ah2, ah3, bh0, bh1);
                        mma_bf16(acc[t][nf], ah0, ah1, ah2, ah3, bl0, bl1);
                        mma_bf16(acc[t][nf], al0, al1, al2, al3, bh0, bh1);
                    }
                }
            }
        }
    }

    // epilogue: direct stores (block covers all r, full j)
#pragma unroll
    for (int t = 0; t < 2; t++) {
        int h = h0 + 2 * t;
        size_t rbase = (size_t)(b * NN + i0 + isub * 16 + g) * 256;
#pragma unroll
        for (int nf = 0; nf < 8; nf++) {
            int col = h * 64 + nf * 8 + 2 * c;
            *(float2*)&out[rbase + col] = make_float2(acc[t][nf][0], acc[t][nf][1]);
            *(float2*)&out[rbase + 8 * 256 + col] = make_float2(acc[t][nf][2], acc[t][nf][3]);
        }
    }
}

// -------- launch --------
extern "C" void kernel_launch(void* const* d_in, const int* in_sizes, int n_in,
                              void* d_out, int out_size) {
    const float* X   = (const float*)d_in[0];
    const int*   adj = (const int*)d_in[1];
    const float* W   = (const float*)d_in[2];
    const float* a   = (const float*)d_in[3];
    float* out = (float*)d_out;

    cudaFuncSetAttribute(k_pv_mma, cudaFuncAttributeMaxDynamicSharedMemorySize, SMEM_PV);

    k_gemm<<<dim3(COUT / 128, (B * NN) / 128, RR), 256>>>(X, W);
    k_split<<<dim3(NN / 32, COUT / 32, RR * B), 256>>>();
    k_lvec<<<(RR * B * NN) / 8, 256>>>(a);
    k_pack<<<(B * NN * 32) / 8, 256>>>(adj);
    k_denom<<<dim3(NN / 8, B), 256>>>();
    k_pv_mma<<<dim3(NN / 64, B), 256, SMEM_PV>>>(out);
}

// round 12
// speedup vs baseline: 1.6490x; 1.0977x over previous
#include <cuda_runtime.h>
#include <math.h>
#include <stdint.h>

#define B    8
#define NN   1024
#define CIN  256
#define COUT 256
#define RR   4
#define HH   4
#define ALPHA 0.2f

// -------- scratch --------
__device__ float g_F[(size_t)RR * B * NN * COUT];
__device__ unsigned g_Fhi[(size_t)RR * B * COUT * NN / 2];  // bf16 pairs, [rb][c][j/2]
__device__ unsigned g_Flo[(size_t)RR * B * COUT * NN / 2];
__device__ unsigned g_Xhi[(size_t)B * NN * CIN / 2];        // [m][k/2] bf16 pairs
__device__ unsigned g_Xlo[(size_t)B * NN * CIN / 2];
__device__ unsigned g_Wthi[RR * COUT * CIN / 2];            // [r][n][k/2]
__device__ unsigned g_Wtlo[RR * COUT * CIN / 2];
__device__ float g_E1 [RR * B * HH * NN];
__device__ float g_E2 [RR * B * HH * NN];
__device__ float g_T  [RR * B * HH * NN];
__device__ float g_A1p[RR * B * HH * NN];
__device__ float g_A2p[RR * B * HH * NN];
__device__ float g_A1 [RR * B * HH * NN];
__device__ float g_A2 [RR * B * HH * NN];
__device__ __align__(16) unsigned g_mask[B * NN * RR * (NN / 32)];

#define LIDX(r, b, h, n) ((((r) * B + (b)) * HH + (h)) * NN + (n))

// -------- helpers --------
__device__ __forceinline__ uint32_t smem_u32(const void* p) {
    uint32_t a;
    asm("{ .reg .u64 t; cvta.to.shared.u64 t, %1; cvt.u32.u64 %0, t; }" : "=r"(a) : "l"(p));
    return a;
}
__device__ __forceinline__ uint32_t sw128(uint32_t o) { return o ^ ((o >> 3) & 0x70); }

__device__ __forceinline__ void ldm_x2(unsigned& r0, unsigned& r1, uint32_t addr) {
    asm volatile("ldmatrix.sync.aligned.m8n8.x2.shared.b16 {%0,%1}, [%2];"
                 : "=r"(r0), "=r"(r1) : "r"(addr));
}
__device__ __forceinline__ void ldm_x4(unsigned& r0, unsigned& r1, unsigned& r2,
                                       unsigned& r3, uint32_t addr) {
    asm volatile("ldmatrix.sync.aligned.m8n8.x4.shared.b16 {%0,%1,%2,%3}, [%4];"
                 : "=r"(r0), "=r"(r1), "=r"(r2), "=r"(r3) : "r"(addr));
}
__device__ __forceinline__ void mma_bf16(float* c, unsigned a0, unsigned a1,
                                         unsigned a2, unsigned a3,
                                         unsigned b0, unsigned b1) {
    asm("mma.sync.aligned.m16n8k16.row.col.f32.bf16.bf16.f32 "
        "{%0,%1,%2,%3}, {%4,%5,%6,%7}, {%8,%9}, {%0,%1,%2,%3};"
        : "+f"(c[0]), "+f"(c[1]), "+f"(c[2]), "+f"(c[3])
        : "r"(a0), "r"(a1), "r"(a2), "r"(a3), "r"(b0), "r"(b1));
}
__device__ __forceinline__ float pvf(unsigned mw, int bit, float e1, float e2,
                                     float T, float A1, float A2) {
    float p = (e1 > T) ? A1 * e1 : A2 * e2;
    return ((mw >> bit) & 1u) ? p : 0.f;
}
__device__ __forceinline__ void split2(float v0, float v1, unsigned& hi, unsigned& lo) {
    unsigned u0 = __float_as_uint(v0), u1 = __float_as_uint(v1);
    hi = __byte_perm(u0, u1, 0x7632);
    float l0 = v0 - __uint_as_float(u0 & 0xFFFF0000u);
    float l1 = v1 - __uint_as_float(u1 & 0xFFFF0000u);
    lo = __byte_perm(__float_as_uint(l0), __float_as_uint(l1), 0x7632);
}

// SMEM layout for k_pv_mma
#define SM_E2   16384
#define SM_MASK 32768
#define SM_FH   43008
#define SM_FL   (43008 + 32768)
#define SMEM_PV (43008 + 65536)

// SMEM layout for k_gemm_mma (dynamic): AH 0, AL 16K, BH 32K, BL 48K
#define GM_AL   16384
#define GM_BH   32768
#define GM_BL   49152
#define SMEM_GM 65536

// -------- kernel 1a: split X -> bf16 hi/lo pair words [m][k/2] --------
__global__ __launch_bounds__(256) void k_splitX(const float* __restrict__ X) {
    int idx = blockIdx.x * 256 + threadIdx.x;       // word index, 1M total
    float2 v = *(const float2*)(X + (size_t)idx * 2);
    unsigned hi, lo;
    split2(v.x, v.y, hi, lo);
    g_Xhi[idx] = hi;
    g_Xlo[idx] = lo;
}

// -------- kernel 1b: split+transpose W -> [r][n][k/2] bf16 hi/lo --------
__global__ __launch_bounds__(256) void k_splitW(const float* __restrict__ W) {
    int idx = blockIdx.x * 256 + threadIdx.x;       // 131072 words
    int kw = idx & 127;
    int n  = (idx >> 7) & 255;
    int r  = idx >> 15;
    float w0 = W[((size_t)r * 256 + 2 * kw) * 256 + n];
    float w1 = W[((size_t)r * 256 + 2 * kw + 1) * 256 + n];
    unsigned hi, lo;
    split2(w0, w1, hi, lo);
    g_Wthi[idx] = hi;
    g_Wtlo[idx] = lo;
}

// -------- kernel 1c: F = X @ W[r] via mma.sync (3-product split) --------
// grid (mtile 64, nhalf 2, r 4); block 256 = 8 warps; warp: 32m x 64n
__global__ __launch_bounds__(256, 2) void k_gemm_mma() {
    extern __shared__ __align__(128) char smem[];
    uint32_t sb = smem_u32(smem);
    int tid = threadIdx.x;
    int wid = tid >> 5, lane = tid & 31;
    int g = lane >> 2, c = lane & 3;
    int m0 = blockIdx.x * 128;
    int n0 = blockIdx.y * 128;
    int r  = blockIdx.z;
    int msub = (wid & 3) * 32;
    int nsub = (wid >> 2) * 64;

    float acc[2][8][4];
#pragma unroll
    for (int mi = 0; mi < 2; mi++)
#pragma unroll
        for (int ni = 0; ni < 8; ni++)
#pragma unroll
            for (int q = 0; q < 4; q++) acc[mi][ni][q] = 0.f;

    int srow = tid >> 1, shalf = tid & 1;

    for (int k0 = 0; k0 < CIN; k0 += 64) {
        __syncthreads();
        {   // stage A (X rows m0..m0+127, k-chunk 64) hi/lo
            const uint4* ph = (const uint4*)(g_Xhi + ((size_t)(m0 + srow) * 128 + k0 / 2 + shalf * 16));
            const uint4* pl = (const uint4*)(g_Xlo + ((size_t)(m0 + srow) * 128 + k0 / 2 + shalf * 16));
#pragma unroll
            for (int q = 0; q < 4; q++) {
                uint32_t off = sw128((uint32_t)(srow * 128 + shalf * 64 + q * 16));
                *(uint4*)(smem + off) = ph[q];
                *(uint4*)(smem + GM_AL + off) = pl[q];
            }
        }
        {   // stage B (Wt rows n0..n0+127, k-chunk 64) hi/lo
            const uint4* ph = (const uint4*)(g_Wthi + ((size_t)(r * 256 + n0 + srow) * 128 + k0 / 2 + shalf * 16));
            const uint4* pl = (const uint4*)(g_Wtlo + ((size_t)(r * 256 + n0 + srow) * 128 + k0 / 2 + shalf * 16));
#pragma unroll
            for (int q = 0; q < 4; q++) {
                uint32_t off = sw128((uint32_t)(srow * 128 + shalf * 64 + q * 16));
                *(uint4*)(smem + GM_BH + off) = ph[q];
                *(uint4*)(smem + GM_BL + off) = pl[q];
            }
        }
        __syncthreads();

#pragma unroll
        for (int ks = 0; ks < 4; ks++) {
#pragma unroll
            for (int mi = 0; mi < 2; mi++) {
                int arow = msub + mi * 16 + (lane & 15);
                uint32_t aoff = sw128((uint32_t)(arow * 128 + ks * 32 + (lane >> 4) * 16));
                unsigned ah0, ah1, ah2, ah3, al0, al1, al2, al3;
                ldm_x4(ah0, ah1, ah2, ah3, sb + aoff);
                ldm_x4(al0, al1, al2, al3, sb + GM_AL + aoff);
#pragma unroll
                for (int ni = 0; ni < 8; ni++) {
                    int brow = nsub + ni * 8 + (lane & 7);
                    uint32_t boff = sw128((uint32_t)(brow * 128 + ks * 32 + ((lane >> 3) & 1) * 16));
                    unsigned bh0, bh1, bl0, bl1;
                    ldm_x2(bh0, bh1, sb + GM_BH + boff);
                    ldm_x2(bl0, bl1, sb + GM_BL + boff);
                    mma_bf16(acc[mi][ni], ah0, ah1, ah2, ah3, bh0, bh1);
                    mma_bf16(acc[mi][ni], ah0, ah1, ah2, ah3, bl0, bl1);
                    mma_bf16(acc[mi][ni], al0, al1, al2, al3, bh0, bh1);
                }
            }
        }
    }

    float* Fo = g_F + (size_t)r * (B * NN) * COUT;
#pragma unroll
    for (int mi = 0; mi < 2; mi++) {
        int m = m0 + msub + mi * 16 + g;
#pragma unroll
        for (int ni = 0; ni < 8; ni++) {
            int col = n0 + nsub + ni * 8 + 2 * c;
            *(float2*)&Fo[(size_t)m * COUT + col] = make_float2(acc[mi][ni][0], acc[mi][ni][1]);
            *(float2*)&Fo[(size_t)(m + 8) * COUT + col] = make_float2(acc[mi][ni][2], acc[mi][ni][3]);
        }
    }
}

// -------- kernel 1d: transpose+split F -> bf16 hi/lo planes [rb][c][j] --------
__global__ __launch_bounds__(256) void k_split() {
    int rb = blockIdx.z;
    int jt = blockIdx.x;
    int ct = blockIdx.y;
    __shared__ float sm[32][33];
    int t = threadIdx.x;
    {
        int tx = t & 31, ty = t >> 5;
#pragma unroll
        for (int u = 0; u < 4; u++) {
            int jj = ty + u * 8;
            sm[jj][tx] = g_F[((size_t)rb * NN + jt * 32 + jj) * COUT + ct * 32 + tx];
        }
    }
    __syncthreads();
    {
        int tx2 = t & 15, cy = t >> 4;
#pragma unroll
        for (int u = 0; u < 2; u++) {
            int c = cy + u * 16;
            float p0 = sm[2 * tx2][c];
            float p1 = sm[2 * tx2 + 1][c];
            unsigned hiw, low;
            split2(p0, p1, hiw, low);
            size_t idx = ((size_t)rb * 256 + ct * 32 + c) * 512 + jt * 16 + tx2;
            g_Fhi[idx] = hiw;
            g_Flo[idx] = low;
        }
    }
}

// -------- kernel 2: li/lj dots + exp factor tables --------
__global__ __launch_bounds__(256) void k_lvec(const float* __restrict__ a) {
    int warp = threadIdx.x >> 5, lane = threadIdx.x & 31;
    int rbn = blockIdx.x * 8 + warp;
    int r = rbn >> 13;
    int bn = rbn & 8191;
    int b = bn >> 10, n = bn & 1023;
    const float* f = g_F + (size_t)rbn * COUT;
#pragma unroll
    for (int h = 0; h < HH; h++) {
        const float* ah = a + (r * HH + h) * 128;
        float f1 = f[h * 64 + lane];
        float f2 = f[h * 64 + 32 + lane];
        float li = f1 * ah[lane]      + f2 * ah[32 + lane];
        float lj = f1 * ah[64 + lane] + f2 * ah[96 + lane];
#pragma unroll
        for (int o = 16; o > 0; o >>= 1) {
            li += __shfl_xor_sync(~0u, li, o);
            lj += __shfl_xor_sync(~0u, lj, o);
        }
        if (lane == 0) {
            int idx = LIDX(r, b, h, n);
            g_E1[idx]  = expf(lj);
            g_E2[idx]  = expf(ALPHA * lj);
            g_T[idx]   = expf(-li);
            g_A1p[idx] = expf(li);
            g_A2p[idx] = expf(ALPHA * li);
        }
    }
}

// -------- kernel 3a: streaming adjacency bit-pack --------
__global__ __launch_bounds__(256) void k_pack(const int* __restrict__ adj) {
    int w    = (blockIdx.x * 256 + threadIdx.x) >> 5;
    int lane = threadIdx.x & 31;
    int jw = w & 31;
    int i  = (w >> 5) & 1023;
    int b  = w >> 15;
    int j  = jw * 32 + lane;
    const int4 av = *(const int4*)(adj + ((size_t)(b * NN + i) * NN + j) * RR);
    unsigned m0 = __ballot_sync(~0u, av.x != 0);
    unsigned m1 = __ballot_sync(~0u, av.y != 0);
    unsigned m2 = __ballot_sync(~0u, av.z != 0);
    unsigned m3 = __ballot_sync(~0u, av.w != 0);
    if (lane < 4) {
        unsigned mv = (lane == 0) ? m0 : (lane == 1) ? m1 : (lane == 2) ? m2 : m3;
        g_mask[(((size_t)b * NN + i) * RR + lane) * (NN / 32) + jw] = mv;
    }
}

// -------- kernel 3b: softmax denominators from packed bits --------
#define JC 256
__global__ __launch_bounds__(256) void k_denom() {
    int b  = blockIdx.y;
    int i0 = blockIdx.x * 8;
    int warp = threadIdx.x >> 5, lane = threadIdx.x & 31;
    int i = i0 + warp;
    int bn = b * NN + i;
    __shared__ float sE1[16][JC];
    __shared__ float sE2[16][JC];
    float T[16], s1[16], s2[16];
#pragma unroll
    for (int rh = 0; rh < 16; rh++) {
        int r = rh >> 2, h = rh & 3;
        T[rh] = g_T[LIDX(r, b, h, i)];
        s1[rh] = 0.f; s2[rh] = 0.f;
    }
    for (int jc = 0; jc < NN; jc += JC) {
        __syncthreads();
        for (int idx = threadIdx.x; idx < 16 * JC; idx += 256) {
            int rh = idx / JC, jj = idx % JC;
            int r = rh >> 2, h = rh & 3;
            int g = LIDX(r, b, h, jc + jj);
            sE1[rh][jj] = g_E1[g];
            sE2[rh][jj] = g_E2[g];
        }
        __syncthreads();
        for (int js = 0; js < JC; js += 32) {
            int jword = (jc + js) >> 5;
            unsigned mw[4];
#pragma unroll
            for (int r = 0; r < 4; r++)
                mw[r] = g_mask[(((size_t)bn) * RR + r) * (NN / 32) + jword];
#pragma unroll
            for (int rh = 0; rh < 16; rh++) {
                if ((mw[rh >> 2] >> lane) & 1u) {
                    float e1 = sE1[rh][js + lane];
                    float e2 = sE2[rh][js + lane];
                    if (e1 > T[rh]) s1[rh] += e1; else s2[rh] += e2;
                }
            }
        }
    }
#pragma unroll
    for (int rh = 0; rh < 16; rh++) {
#pragma unroll
        for (int o = 16; o > 0; o >>= 1) {
            s1[rh] += __shfl_xor_sync(~0u, s1[rh], o);
            s2[rh] += __shfl_xor_sync(~0u, s2[rh], o);
        }
    }
#pragma unroll
    for (int rh = 0; rh < 16; rh++) {
        if (lane == rh) {
            int r = rh >> 2, h = rh & 3;
            int idx = LIDX(r, b, h, i);
            float A1 = g_A1p[idx], A2 = g_A2p[idx];
            float den = A1 * s1[rh] + A2 * s2[rh];
            if (!(den > 0.f)) { den = 1.f; A1 = 0.f; A2 = 0.f; }
            g_A1[idx] = A1 / den;
            g_A2[idx] = A2 / den;
        }
    }
}

// -------- kernel 4: PV via mma.sync bf16 (3-product hi/lo split) --------
__global__ __launch_bounds__(256, 1) void k_pv_mma(float* __restrict__ out) {
    extern __shared__ __align__(128) char smem[];
    float* sE1 = (float*)(smem);
    float* sE2 = (float*)(smem + SM_E2);
    unsigned* smask = (unsigned*)(smem + SM_MASK);   // [64][33] padded
    uint32_t sb = smem_u32(smem);

    int b = blockIdx.y, i0 = blockIdx.x * 64;
    int tid = threadIdx.x;
    int wid = tid >> 5, lane = tid & 31;
    int g = lane >> 2, c = lane & 3;
    int isub = wid & 3;
    int h0 = wid >> 2;
    int rowl = isub * 16 + g;
    int rowh = rowl + 8;

    float acc[2][8][4];
#pragma unroll
    for (int t = 0; t < 2; t++)
#pragma unroll
        for (int nf = 0; nf < 8; nf++)
#pragma unroll
            for (int q = 0; q < 4; q++) acc[t][nf][q] = 0.f;

    for (int r = 0; r < RR; r++) {
        int rb = r * B + b;
        __syncthreads();
#pragma unroll
        for (int u = 0; u < 16; u++) {
            int idx = u * 256 + tid;
            sE1[idx] = g_E1[rb * 4096 + idx];
            sE2[idx] = g_E2[rb * 4096 + idx];
        }
#pragma unroll
        for (int u = 0; u < 8; u++) {
            int idx = u * 256 + tid;
            int row = idx >> 5, w = idx & 31;
            smask[row * 33 + w] =
                g_mask[(((size_t)b * NN + i0 + row) * RR + r) * 32 + w];
        }
        float Tc[2][2], A1c[2][2], A2c[2][2];
#pragma unroll
        for (int t = 0; t < 2; t++) {
            int h = h0 + 2 * t;
            int base = rb * 4096 + h * 1024 + i0;
            Tc[t][0]  = g_T [base + rowl];  Tc[t][1]  = g_T [base + rowh];
            A1c[t][0] = g_A1[base + rowl];  A1c[t][1] = g_A1[base + rowh];
            A2c[t][0] = g_A2[base + rowl];  A2c[t][1] = g_A2[base + rowh];
        }

        for (int jc = 0; jc < NN; jc += 64) {
            __syncthreads();
            {
                const uint4* ph = (const uint4*)(g_Fhi + ((size_t)rb * 256 + tid) * 512 + jc / 2);
                const uint4* pl = (const uint4*)(g_Flo + ((size_t)rb * 256 + tid) * 512 + jc / 2);
#pragma unroll
                for (int q = 0; q < 8; q++) {
                    uint32_t off = sw128((uint32_t)(tid * 128 + q * 16));
                    *(uint4*)(smem + SM_FH + off) = ph[q];
                    *(uint4*)(smem + SM_FL + off) = pl[q];
                }
            }
            __syncthreads();

#pragma unroll
            for (int kf = 0; kf < 4; kf++) {
                int jb = jc + kf * 16;
                unsigned mwl = smask[rowl * 33 + (jb >> 5)];
                unsigned mwh = smask[rowh * 33 + (jb >> 5)];
                int bo = jb & 31;
#pragma unroll
                for (int t = 0; t < 2; t++) {
                    int h = h0 + 2 * t;
                    int eb = h * 1024 + jb + 2 * c;
                    float2 e1a = *(float2*)&sE1[eb];
                    float2 e1b = *(float2*)&sE1[eb + 8];
                    float2 e2a = *(float2*)&sE2[eb];
                    float2 e2b = *(float2*)&sE2[eb + 8];
                    float p00 = pvf(mwl, bo + 2*c,     e1a.x, e2a.x, Tc[t][0], A1c[t][0], A2c[t][0]);
                    float p01 = pvf(mwl, bo + 2*c + 1, e1a.y, e2a.y, Tc[t][0], A1c[t][0], A2c[t][0]);
                    float p02 = pvf(mwl, bo + 8 + 2*c,     e1b.x, e2b.x, Tc[t][0], A1c[t][0], A2c[t][0]);
                    float p03 = pvf(mwl, bo + 8 + 2*c + 1, e1b.y, e2b.y, Tc[t][0], A1c[t][0], A2c[t][0]);
                    float p10 = pvf(mwh, bo + 2*c,     e1a.x, e2a.x, Tc[t][1], A1c[t][1], A2c[t][1]);
                    float p11 = pvf(mwh, bo + 2*c + 1, e1a.y, e2a.y, Tc[t][1], A1c[t][1], A2c[t][1]);
                    float p12 = pvf(mwh, bo + 8 + 2*c,     e1b.x, e2b.x, Tc[t][1], A1c[t][1], A2c[t][1]);
                    float p13 = pvf(mwh, bo + 8 + 2*c + 1, e1b.y, e2b.y, Tc[t][1], A1c[t][1], A2c[t][1]);
                    unsigned ah0, ah1, ah2, ah3, al0, al1, al2, al3;
                    split2(p00, p01, ah0, al0);
                    split2(p10, p11, ah1, al1);
                    split2(p02, p03, ah2, al2);
                    split2(p12, p13, ah3, al3);
#pragma unroll
                    for (int nf = 0; nf < 8; nf++) {
                        int lr = h * 64 + nf * 8 + (lane & 7);
                        int jo2 = kf * 32 + ((lane >> 3) & 1) * 16;
                        uint32_t off = sw128((uint32_t)(lr * 128 + jo2));
                        unsigned bh0, bh1, bl0, bl1;
                        ldm_x2(bh0, bh1, sb + SM_FH + off);
                        ldm_x2(bl0, bl1, sb + SM_FL + off);
                        mma_bf16(acc[t][nf], ah0, ah1, ah2, ah3, bh0, bh1);
                        mma_bf16(acc[t][nf], ah0, ah1, ah2, ah3, bl0, bl1);
                        mma_bf16(acc[t][nf], al0, al1, al2, al3, bh0, bh1);
                    }
                }
            }
        }
    }

#pragma unroll
    for (int t = 0; t < 2; t++) {
        int h = h0 + 2 * t;
        size_t rbase = (size_t)(b * NN + i0 + isub * 16 + g) * 256;
#pragma unroll
        for (int nf = 0; nf < 8; nf++) {
            int col = h * 64 + nf * 8 + 2 * c;
            *(float2*)&out[rbase + col] = make_float2(acc[t][nf][0], acc[t][nf][1]);
            *(float2*)&out[rbase + 8 * 256 + col] = make_float2(acc[t][nf][2], acc[t][nf][3]);
        }
    }
}

// -------- launch --------
extern "C" void kernel_launch(void* const* d_in, const int* in_sizes, int n_in,
                              void* d_out, int out_size) {
    const float* X   = (const float*)d_in[0];
    const int*   adj = (const int*)d_in[1];
    const float* W   = (const float*)d_in[2];
    const float* a   = (const float*)d_in[3];
    float* out = (float*)d_out;

    cudaFuncSetAttribute(k_pv_mma, cudaFuncAttributeMaxDynamicSharedMemorySize, SMEM_PV);
    cudaFuncSetAttribute(k_gemm_mma, cudaFuncAttributeMaxDynamicSharedMemorySize, SMEM_GM);

    k_splitX<<<(B * NN * CIN / 2) / 256, 256>>>(X);
    k_splitW<<<(RR * COUT * CIN / 2) / 256, 256>>>(W);
    k_gemm_mma<<<dim3((B * NN) / 128, 2, RR), 256, SMEM_GM>>>();
    k_split<<<dim3(NN / 32, COUT / 32, RR * B), 256>>>();
    k_lvec<<<(RR * B * NN) / 8, 256>>>(a);
    k_pack<<<(B * NN * 32) / 8, 256>>>(adj);
    k_denom<<<dim3(NN / 8, B), 256>>>();
    k_pv_mma<<<dim3(NN / 64, B), 256, SMEM_PV>>>(out);
}